// round 11
// baseline (speedup 1.0000x reference)
#include <cuda_runtime.h>
#include <math.h>

// Problem shape (fixed by the reference)
#define NSAMP 2048
#define OBS   48
// Layers: (out, in)
// L0: 512 x 48   L1: 256 x 512   L2: 128 x 256   L3: 12 x 128

// Inter-layer activation scratch (device globals: allocation-free).
__device__ __align__(16) float g_a0[NSAMP * 512];
__device__ __align__(16) float g_a1[NSAMP * 256];
// L3 partial dots: [n][r (12)][cta (8)]
__device__ __align__(16) float g_part[NSAMP * 12 * 8];

__device__ __forceinline__ float elu(float s) {
    return (s > 0.0f) ? s : (__expf(s) - 1.0f);
}

// ---------------------------------------------------------------------------
// L0: obs-norm fused with 512x48 layer. 4-lane groups: lane gl loads 3
// contiguous float4 of one row; warp covers 8 rows = 1536B fully coalesced.
// 256 threads, 128 rows/CTA -> 4 CTAs/sample (grid 8192).
// ---------------------------------------------------------------------------
__global__ void __launch_bounds__(256)
k_l0(const float* __restrict__ obs, const float* __restrict__ mean,
     const float* __restrict__ stdv, const float* __restrict__ W0,
     const float* __restrict__ b0) {
    const int b  = blockIdx.x;
    const int n  = b >> 2;             // sample
    const int rb = (b & 3) * 128;      // row base within sample
    const int tid = threadIdx.x;

    __shared__ __align__(16) float xs[OBS];
    if (tid < OBS) {
        const int i = n * OBS + tid;
        float v = (obs[i] - mean[i]) / stdv[i];
        xs[tid] = fminf(fmaxf(v, -5.0f), 5.0f);
    }
    __syncthreads();

    const int wid  = tid >> 5;         // 8 warps
    const int lane = tid & 31;
    const int g    = lane >> 2;        // 8 row-groups per warp
    const int gl   = lane & 3;         // 4 lanes per row

    const float4* __restrict__ xv = reinterpret_cast<const float4*>(xs);
    const float4 v0 = xv[gl * 3 + 0];
    const float4 v1 = xv[gl * 3 + 1];
    const float4 v2 = xv[gl * 3 + 2];

    const float* __restrict__ W  = W0 + (size_t)n * 512 * 48;
    const float* __restrict__ bb = b0 + (size_t)n * 512;
    float* __restrict__ y = g_a0 + (size_t)n * 512;

    const int r0 = rb + wid * 16 + g;
    const int r1 = r0 + 8;

    const float4* __restrict__ Wr0 =
        reinterpret_cast<const float4*>(W + (size_t)r0 * 48) + gl * 3;
    const float4* __restrict__ Wr1 =
        reinterpret_cast<const float4*>(W + (size_t)r1 * 48) + gl * 3;

    float bias0 = 0.f, bias1 = 0.f;
    if (gl == 0) { bias0 = __ldcs(bb + r0); bias1 = __ldcs(bb + r1); }

    float4 a0 = __ldcs(Wr0 + 0), a1 = __ldcs(Wr0 + 1), a2 = __ldcs(Wr0 + 2);
    float4 c0 = __ldcs(Wr1 + 0), c1 = __ldcs(Wr1 + 1), c2 = __ldcs(Wr1 + 2);

    float s0 = fmaf(a0.x, v0.x, fmaf(a0.y, v0.y, fmaf(a0.z, v0.z, a0.w * v0.w)));
    s0 = fmaf(a1.x, v1.x, fmaf(a1.y, v1.y, fmaf(a1.z, v1.z, fmaf(a1.w, v1.w, s0))));
    s0 = fmaf(a2.x, v2.x, fmaf(a2.y, v2.y, fmaf(a2.z, v2.z, fmaf(a2.w, v2.w, s0))));
    float s1 = fmaf(c0.x, v0.x, fmaf(c0.y, v0.y, fmaf(c0.z, v0.z, c0.w * v0.w)));
    s1 = fmaf(c1.x, v1.x, fmaf(c1.y, v1.y, fmaf(c1.z, v1.z, fmaf(c1.w, v1.w, s1))));
    s1 = fmaf(c2.x, v2.x, fmaf(c2.y, v2.y, fmaf(c2.z, v2.z, fmaf(c2.w, v2.w, s1))));

    s0 += __shfl_xor_sync(0xffffffffu, s0, 1);
    s1 += __shfl_xor_sync(0xffffffffu, s1, 1);
    s0 += __shfl_xor_sync(0xffffffffu, s0, 2);
    s1 += __shfl_xor_sync(0xffffffffu, s1, 2);

    if (gl == 0) {
        y[r0] = elu(s0 + bias0);
        y[r1] = elu(s1 + bias1);
    }
}

// ---------------------------------------------------------------------------
// L1: 256 x 512. Warp per row-pair, 32 rows/CTA -> 8 CTAs/sample.
// ---------------------------------------------------------------------------
__global__ void __launch_bounds__(256, 8)
k_l1(const float* __restrict__ Wg, const float* __restrict__ bg,
     const float* __restrict__ xg, float* __restrict__ yg) {
    constexpr int IN = 512, NV = IN / 4;
    const int b  = blockIdx.x;
    const int n  = b >> 3;
    const int rb = (b & 7) * 32;
    const int tid = threadIdx.x;
    const int wid = tid >> 5;
    const int gl  = tid & 31;

    __shared__ __align__(16) float xs[IN];
    {
        const float4* __restrict__ src =
            reinterpret_cast<const float4*>(xg + (size_t)n * IN);
        if (tid < NV) reinterpret_cast<float4*>(xs)[tid] = src[tid];
    }
    __syncthreads();

    const float4* __restrict__ xv = reinterpret_cast<const float4*>(xs);
    const float* __restrict__ W = Wg + (size_t)n * 256 * IN;
    const float* __restrict__ bb = bg + (size_t)n * 256;
    float* __restrict__ y = yg + (size_t)n * 256;

    #pragma unroll
    for (int r0 = rb + wid; r0 < rb + 32; r0 += 16) {
        const int r1 = r0 + 8;
        float bias0 = __ldcs(bb + r0);
        float bias1 = __ldcs(bb + r1);
        const float4* __restrict__ Wr0 =
            reinterpret_cast<const float4*>(W + (size_t)r0 * IN);
        const float4* __restrict__ Wr1 =
            reinterpret_cast<const float4*>(W + (size_t)r1 * IN);
        float s0 = 0.0f, s1 = 0.0f;
        #pragma unroll
        for (int j = gl; j < NV; j += 32) {
            float4 w0 = __ldcs(Wr0 + j);
            float4 w1 = __ldcs(Wr1 + j);
            float4 v  = xv[j];
            s0 = fmaf(w0.x, v.x, s0);
            s0 = fmaf(w0.y, v.y, s0);
            s0 = fmaf(w0.z, v.z, s0);
            s0 = fmaf(w0.w, v.w, s0);
            s1 = fmaf(w1.x, v.x, s1);
            s1 = fmaf(w1.y, v.y, s1);
            s1 = fmaf(w1.z, v.z, s1);
            s1 = fmaf(w1.w, v.w, s1);
        }
        #pragma unroll
        for (int o = 16; o >= 1; o >>= 1) {
            s0 += __shfl_xor_sync(0xffffffffu, s0, o);
            s1 += __shfl_xor_sync(0xffffffffu, s1, o);
        }
        if (gl == 0) {
            y[r0] = elu(s0 + bias0);
            y[r1] = elu(s1 + bias1);
        }
    }
}

// ---------------------------------------------------------------------------
// L2 (128x256) with fused L3 partial epilogue. 16 rows/CTA -> 8 CTAs/sample.
// After computing its 16 h values, warp 0 loads the 12x16 W3 slice for this
// CTA's columns and writes 12 partial dots to g_part[n][r][cta].
// ---------------------------------------------------------------------------
__global__ void __launch_bounds__(256, 8)
k_l2(const float* __restrict__ Wg, const float* __restrict__ bg,
     const float* __restrict__ W3, const float* __restrict__ xg) {
    constexpr int IN = 256, NV = IN / 4;
    const int b  = blockIdx.x;
    const int n  = b >> 3;
    const int sub = b & 7;             // which 16-row slice
    const int rb = sub * 16;
    const int tid = threadIdx.x;
    const int wid = tid >> 5;
    const int gl  = tid & 31;

    __shared__ __align__(16) float xs[IN];
    __shared__ __align__(16) float hs[16];
    {
        const float4* __restrict__ src =
            reinterpret_cast<const float4*>(xg + (size_t)n * IN);
        if (tid < NV) reinterpret_cast<float4*>(xs)[tid] = src[tid];
    }
    __syncthreads();

    const float4* __restrict__ xv = reinterpret_cast<const float4*>(xs);
    const float* __restrict__ W = Wg + (size_t)n * 128 * IN;
    const float* __restrict__ bb = bg + (size_t)n * 128;

    // 16 rows: warp wid does rows rb+wid and rb+wid+8
    {
        const int r0 = rb + wid;
        const int r1 = r0 + 8;
        float bias0 = __ldcs(bb + r0);
        float bias1 = __ldcs(bb + r1);
        const float4* __restrict__ Wr0 =
            reinterpret_cast<const float4*>(W + (size_t)r0 * IN);
        const float4* __restrict__ Wr1 =
            reinterpret_cast<const float4*>(W + (size_t)r1 * IN);
        float s0 = 0.0f, s1 = 0.0f;
        #pragma unroll
        for (int j = gl; j < NV; j += 32) {
            float4 w0 = __ldcs(Wr0 + j);
            float4 w1 = __ldcs(Wr1 + j);
            float4 v  = xv[j];
            s0 = fmaf(w0.x, v.x, s0);
            s0 = fmaf(w0.y, v.y, s0);
            s0 = fmaf(w0.z, v.z, s0);
            s0 = fmaf(w0.w, v.w, s0);
            s1 = fmaf(w1.x, v.x, s1);
            s1 = fmaf(w1.y, v.y, s1);
            s1 = fmaf(w1.z, v.z, s1);
            s1 = fmaf(w1.w, v.w, s1);
        }
        #pragma unroll
        for (int o = 16; o >= 1; o >>= 1) {
            s0 += __shfl_xor_sync(0xffffffffu, s0, o);
            s1 += __shfl_xor_sync(0xffffffffu, s1, o);
        }
        if (gl == 0) {
            hs[wid]     = elu(s0 + bias0);
            hs[wid + 8] = elu(s1 + bias1);
        }
    }
    __syncthreads();

    // L3 partial epilogue on warp 0: lanes 0..15 hold h; for each of 12
    // output rows, dot with W3[r][rb..rb+16), fixed-order reduce.
    if (wid == 0) {
        const float h = (gl < 16) ? hs[gl] : 0.0f;
        const float* __restrict__ W3n = W3 + (size_t)n * 12 * 128 + rb;
        float p[12];
        #pragma unroll
        for (int r = 0; r < 12; r++) {
            float w = (gl < 16) ? __ldcs(W3n + r * 128 + gl) : 0.0f;
            p[r] = w * h;
        }
        #pragma unroll
        for (int o = 8; o >= 1; o >>= 1) {
            #pragma unroll
            for (int r = 0; r < 12; r++)
                p[r] += __shfl_xor_sync(0xffffffffu, p[r], o);
        }
        if (gl == 0) {
            float* __restrict__ dst = g_part + (size_t)n * 96 + sub;
            #pragma unroll
            for (int r = 0; r < 12; r++)
                dst[r * 8] = p[r];
        }
    }
}

// ---------------------------------------------------------------------------
// Final: out[n][r] = tanh(b3[n][r] + sum_{c=0..7} g_part[n][r][c]).
// One thread per output (24576 threads). Fixed summation order.
// ---------------------------------------------------------------------------
__global__ void __launch_bounds__(256)
k_fin(const float* __restrict__ b3, float* __restrict__ out) {
    const int idx = blockIdx.x * 256 + threadIdx.x;   // [0, 24576)
    if (idx >= NSAMP * 12) return;
    const float4* __restrict__ pv =
        reinterpret_cast<const float4*>(g_part + (size_t)idx * 8);
    float4 p0 = pv[0];
    float4 p1 = pv[1];
    float s = ((p0.x + p0.y) + (p0.z + p0.w)) +
              ((p1.x + p1.y) + (p1.z + p1.w));
    out[idx] = tanhf(s + __ldcs(b3 + idx));
}

extern "C" void kernel_launch(void* const* d_in, const int* in_sizes, int n_in,
                              void* d_out, int out_size) {
    const float* obs  = (const float*)d_in[0];
    const float* mean = (const float*)d_in[1];
    const float* stdv = (const float*)d_in[2];
    const float* W0   = (const float*)d_in[3];
    const float* b0   = (const float*)d_in[4];
    const float* W1   = (const float*)d_in[5];
    const float* b1   = (const float*)d_in[6];
    const float* W2   = (const float*)d_in[7];
    const float* b2   = (const float*)d_in[8];
    const float* W3   = (const float*)d_in[9];
    const float* b3   = (const float*)d_in[10];
    float* out = (float*)d_out;

    float* a0;  cudaGetSymbolAddress((void**)&a0, g_a0);
    float* a1;  cudaGetSymbolAddress((void**)&a1, g_a1);

    // L0: 4 CTAs/sample
    k_l0<<<NSAMP * 4, 256>>>(obs, mean, stdv, W0, b0);
    // L1: 8 CTAs/sample
    k_l1<<<NSAMP * 8, 256>>>(W1, b1, a0, a1);
    // L2 + fused L3 partials: 8 CTAs/sample
    k_l2<<<NSAMP * 8, 256>>>(W2, b2, W3, a1);
    // Final reduce + tanh: 1 thread/output
    k_fin<<<(NSAMP * 12 + 255) / 256, 256>>>(b3, out);
}

// round 12
// speedup vs baseline: 1.0740x; 1.0740x over previous
#include <cuda_runtime.h>
#include <math.h>

// Problem shape (fixed by the reference)
#define NSAMP 2048
#define OBS   48
// Layers: (out, in)
// L0: 512 x 48   L1: 256 x 512   L2: 128 x 256   L3: 12 x 128

#define HALF (NSAMP / 2)

// Inter-layer activation scratch (device globals: allocation-free).
__device__ __align__(16) float g_a0[NSAMP * 512];
__device__ __align__(16) float g_a1[NSAMP * 256];
__device__ __align__(16) float g_a2[NSAMP * 128];

__device__ __forceinline__ float elu(float s) {
    return (s > 0.0f) ? s : (__expf(s) - 1.0f);
}

// ---------------------------------------------------------------------------
// L0: obs-norm fused with 512x48 layer. 4-lane groups, 128 rows/CTA
// -> 4 CTAs/sample. n0 = sample offset for this chain.
// ---------------------------------------------------------------------------
__global__ void __launch_bounds__(256)
k_l0(const float* __restrict__ obs, const float* __restrict__ mean,
     const float* __restrict__ stdv, const float* __restrict__ W0,
     const float* __restrict__ b0, int n0) {
    const int b  = blockIdx.x;
    const int n  = n0 + (b >> 2);
    const int rb = (b & 3) * 128;
    const int tid = threadIdx.x;

    __shared__ __align__(16) float xs[OBS];
    if (tid < OBS) {
        const int i = n * OBS + tid;
        float v = (obs[i] - mean[i]) / stdv[i];
        xs[tid] = fminf(fmaxf(v, -5.0f), 5.0f);
    }
    __syncthreads();

    const int wid  = tid >> 5;
    const int lane = tid & 31;
    const int g    = lane >> 2;
    const int gl   = lane & 3;

    const float4* __restrict__ xv = reinterpret_cast<const float4*>(xs);
    const float4 v0 = xv[gl * 3 + 0];
    const float4 v1 = xv[gl * 3 + 1];
    const float4 v2 = xv[gl * 3 + 2];

    const float* __restrict__ W  = W0 + (size_t)n * 512 * 48;
    const float* __restrict__ bb = b0 + (size_t)n * 512;
    float* __restrict__ y = g_a0 + (size_t)n * 512;

    const int r0 = rb + wid * 16 + g;
    const int r1 = r0 + 8;

    const float4* __restrict__ Wr0 =
        reinterpret_cast<const float4*>(W + (size_t)r0 * 48) + gl * 3;
    const float4* __restrict__ Wr1 =
        reinterpret_cast<const float4*>(W + (size_t)r1 * 48) + gl * 3;

    float bias0 = 0.f, bias1 = 0.f;
    if (gl == 0) { bias0 = __ldcs(bb + r0); bias1 = __ldcs(bb + r1); }

    float4 a0 = __ldcs(Wr0 + 0), a1 = __ldcs(Wr0 + 1), a2 = __ldcs(Wr0 + 2);
    float4 c0 = __ldcs(Wr1 + 0), c1 = __ldcs(Wr1 + 1), c2 = __ldcs(Wr1 + 2);

    float s0 = fmaf(a0.x, v0.x, fmaf(a0.y, v0.y, fmaf(a0.z, v0.z, a0.w * v0.w)));
    s0 = fmaf(a1.x, v1.x, fmaf(a1.y, v1.y, fmaf(a1.z, v1.z, fmaf(a1.w, v1.w, s0))));
    s0 = fmaf(a2.x, v2.x, fmaf(a2.y, v2.y, fmaf(a2.z, v2.z, fmaf(a2.w, v2.w, s0))));
    float s1 = fmaf(c0.x, v0.x, fmaf(c0.y, v0.y, fmaf(c0.z, v0.z, c0.w * v0.w)));
    s1 = fmaf(c1.x, v1.x, fmaf(c1.y, v1.y, fmaf(c1.z, v1.z, fmaf(c1.w, v1.w, s1))));
    s1 = fmaf(c2.x, v2.x, fmaf(c2.y, v2.y, fmaf(c2.z, v2.z, fmaf(c2.w, v2.w, s1))));

    s0 += __shfl_xor_sync(0xffffffffu, s0, 1);
    s1 += __shfl_xor_sync(0xffffffffu, s1, 1);
    s0 += __shfl_xor_sync(0xffffffffu, s0, 2);
    s1 += __shfl_xor_sync(0xffffffffu, s1, 2);

    if (gl == 0) {
        y[r0] = elu(s0 + bias0);
        y[r1] = elu(s1 + bias1);
    }
}

// ---------------------------------------------------------------------------
// Generic hidden layer: OUT x IN, warp per row-pair, ROWS_PER_CTA rows/CTA.
// ---------------------------------------------------------------------------
template <int OUT, int IN, int ROWS_PER_CTA, bool ACT>
__global__ void __launch_bounds__(256, 8)
k_layer(const float* __restrict__ Wg, const float* __restrict__ bg,
        const float* __restrict__ xg, float* __restrict__ yg, int n0) {
    constexpr int CTAS_PER_SAMPLE = OUT / ROWS_PER_CTA;
    constexpr int NV = IN / 4;
    const int b  = blockIdx.x;
    const int n  = n0 + b / CTAS_PER_SAMPLE;
    const int rb = (b % CTAS_PER_SAMPLE) * ROWS_PER_CTA;
    const int tid = threadIdx.x;
    const int wid = tid >> 5;
    const int gl  = tid & 31;

    __shared__ __align__(16) float xs[IN];
    {
        const float4* __restrict__ src =
            reinterpret_cast<const float4*>(xg + (size_t)n * IN);
        if (tid < NV) reinterpret_cast<float4*>(xs)[tid] = src[tid];
    }
    __syncthreads();

    const float4* __restrict__ xv = reinterpret_cast<const float4*>(xs);
    const float* __restrict__ W = Wg + (size_t)n * OUT * IN;
    const float* __restrict__ bb = bg + (size_t)n * OUT;
    float* __restrict__ y = yg + (size_t)n * OUT;

    #pragma unroll
    for (int r0 = rb + wid; r0 < rb + ROWS_PER_CTA; r0 += 16) {
        const int r1 = r0 + 8;
        float bias0 = __ldcs(bb + r0);
        float bias1 = __ldcs(bb + r1);
        const float4* __restrict__ Wr0 =
            reinterpret_cast<const float4*>(W + (size_t)r0 * IN);
        const float4* __restrict__ Wr1 =
            reinterpret_cast<const float4*>(W + (size_t)r1 * IN);
        float s0 = 0.0f, s1 = 0.0f;
        #pragma unroll
        for (int j = gl; j < NV; j += 32) {
            float4 w0 = __ldcs(Wr0 + j);
            float4 w1 = __ldcs(Wr1 + j);
            float4 v  = xv[j];
            s0 = fmaf(w0.x, v.x, s0);
            s0 = fmaf(w0.y, v.y, s0);
            s0 = fmaf(w0.z, v.z, s0);
            s0 = fmaf(w0.w, v.w, s0);
            s1 = fmaf(w1.x, v.x, s1);
            s1 = fmaf(w1.y, v.y, s1);
            s1 = fmaf(w1.z, v.z, s1);
            s1 = fmaf(w1.w, v.w, s1);
        }
        #pragma unroll
        for (int o = 16; o >= 1; o >>= 1) {
            s0 += __shfl_xor_sync(0xffffffffu, s0, o);
            s1 += __shfl_xor_sync(0xffffffffu, s1, o);
        }
        if (gl == 0) {
            s0 += bias0;
            s1 += bias1;
            if (ACT) { s0 = elu(s0); s1 = elu(s1); }
            y[r0] = s0;
            y[r1] = s1;
        }
    }
}

// ---------------------------------------------------------------------------
// L3: 12 x 128 + tanh. One WARP per sample; 8 samples per 256-thread CTA.
// ---------------------------------------------------------------------------
__global__ void __launch_bounds__(256)
k_l3(const float* __restrict__ W3, const float* __restrict__ b3,
     float* __restrict__ out, int n0) {
    const int tid  = threadIdx.x;
    const int lane = tid & 31;
    const int n    = n0 + blockIdx.x * 8 + (tid >> 5);

    const float4* __restrict__ xv =
        reinterpret_cast<const float4*>(g_a2 + (size_t)n * 128);
    const float4* __restrict__ Wv =
        reinterpret_cast<const float4*>(W3 + (size_t)n * 12 * 128);

    float bias = (lane < 12) ? __ldcs(b3 + n * 12 + lane) : 0.0f;
    float4 v = xv[lane];

    float s[12];
    #pragma unroll
    for (int r = 0; r < 12; r++) {
        float4 w = __ldcs(Wv + r * 32 + lane);
        s[r] = fmaf(w.x, v.x, fmaf(w.y, v.y, fmaf(w.z, v.z, w.w * v.w)));
    }
    #pragma unroll
    for (int o = 16; o >= 1; o >>= 1) {
        #pragma unroll
        for (int r = 0; r < 12; r++)
            s[r] += __shfl_xor_sync(0xffffffffu, s[r], o);
    }

    float mine = 0.0f;
    #pragma unroll
    for (int r = 0; r < 12; r++)
        if (lane == r) mine = s[r];
    if (lane < 12)
        out[n * 12 + lane] = tanhf(mine + bias);
}

static void launch_chain(cudaStream_t st, int n0,
                         const float* obs, const float* mean, const float* stdv,
                         const float* W0, const float* b0,
                         const float* W1, const float* b1,
                         const float* W2, const float* b2,
                         const float* W3, const float* b3,
                         float* a0, float* a1, float* a2, float* out) {
    k_l0<<<HALF * 4, 256, 0, st>>>(obs, mean, stdv, W0, b0, n0);
    k_layer<256, 512, 32, true><<<HALF * 8, 256, 0, st>>>(W1, b1, a0, a1, n0);
    k_layer<128, 256, 16, true><<<HALF * 8, 256, 0, st>>>(W2, b2, a1, a2, n0);
    k_l3<<<HALF / 8, 256, 0, st>>>(W3, b3, out, n0);
}

extern "C" void kernel_launch(void* const* d_in, const int* in_sizes, int n_in,
                              void* d_out, int out_size) {
    const float* obs  = (const float*)d_in[0];
    const float* mean = (const float*)d_in[1];
    const float* stdv = (const float*)d_in[2];
    const float* W0   = (const float*)d_in[3];
    const float* b0   = (const float*)d_in[4];
    const float* W1   = (const float*)d_in[5];
    const float* b1   = (const float*)d_in[6];
    const float* W2   = (const float*)d_in[7];
    const float* b2   = (const float*)d_in[8];
    const float* W3   = (const float*)d_in[9];
    const float* b3   = (const float*)d_in[10];
    float* out = (float*)d_out;

    float* a0;  cudaGetSymbolAddress((void**)&a0, g_a0);
    float* a1;  cudaGetSymbolAddress((void**)&a1, g_a1);
    float* a2;  cudaGetSymbolAddress((void**)&a2, g_a2);

    // One-time host-side resources (host memory only; no device allocs).
    static cudaStream_t s1 = nullptr;
    static cudaEvent_t ev_fork = nullptr, ev_join = nullptr;
    if (s1 == nullptr) {
        cudaStreamCreateWithFlags(&s1, cudaStreamNonBlocking);
        cudaEventCreateWithFlags(&ev_fork, cudaEventDisableTiming);
        cudaEventCreateWithFlags(&ev_join, cudaEventDisableTiming);
    }

    // Fork: side stream joins the (captured) default stream.
    cudaEventRecord(ev_fork, 0);
    cudaStreamWaitEvent(s1, ev_fork, 0);

    // Chain A (samples [0, HALF)) on the default stream,
    // Chain B (samples [HALF, NSAMP)) on s1 — independent, co-scheduled.
    launch_chain(0,  0,    obs, mean, stdv, W0, b0, W1, b1, W2, b2, W3, b3,
                 a0, a1, a2, out);
    launch_chain(s1, HALF, obs, mean, stdv, W0, b0, W1, b1, W2, b2, W3, b3,
                 a0, a1, a2, out);

    // Join: default stream waits for the side chain.
    cudaEventRecord(ev_join, s1);
    cudaStreamWaitEvent(0, ev_join, 0);
}